// round 3
// baseline (speedup 1.0000x reference)
#include <cuda_runtime.h>

#define H 1024
#define V 50257
#define LCTX 4096

// ---------------- device scratch (allocation-free) ----------------
__device__ float g_e[LCTX];     // attention scores
__device__ float g_a[LCTX];     // softmax weights (16B-aligned copy)
__device__ float g_cat[2 * H];  // [emb ; context]
__device__ float g_x[H];        // projected input
__device__ float g_gi[3 * H];   // W_ih @ x + b_ih
__device__ float g_gh[3 * H];   // W_hh @ s_prev + b_hh
__device__ float g_h[H];        // h_new (aligned copy for logits GEMV)

// ---------------- embedding gather + zero context accumulator ----------------
__global__ void emb_kernel(const int* __restrict__ y, const float* __restrict__ emb_W) {
    int i = blockIdx.x * blockDim.x + threadIdx.x;  // 0 .. 2H-1
    if (i < H) {
        g_cat[i] = emb_W[(size_t)y[0] * H + i];
    } else if (i < 2 * H) {
        g_cat[i] = 0.0f;  // context accumulated via atomics
    }
}

// ---------------- generic warp-per-row GEMV: out[r] = W[r,:].v (+ bias) ----------------
template <int COLS>
__global__ void gemv_kernel(const float* __restrict__ W, const float* __restrict__ v,
                            const float* __restrict__ bias, float* __restrict__ out,
                            int nrows) {
    constexpr int C4 = COLS / 4;
    __shared__ float4 sv[C4];
    for (int i = threadIdx.x; i < C4; i += blockDim.x)
        sv[i] = reinterpret_cast<const float4*>(v)[i];
    __syncthreads();

    int row = (blockIdx.x * blockDim.x + threadIdx.x) >> 5;
    if (row >= nrows) return;
    int lane = threadIdx.x & 31;

    const float4* Wr = reinterpret_cast<const float4*>(W) + (size_t)row * C4;
    float s = 0.0f;
#pragma unroll
    for (int i = 0; i < C4 / 32; ++i) {
        float4 w = __ldg(&Wr[lane + i * 32]);
        float4 x = sv[lane + i * 32];
        s = fmaf(w.x, x.x, s);
        s = fmaf(w.y, x.y, s);
        s = fmaf(w.z, x.z, s);
        s = fmaf(w.w, x.w, s);
    }
#pragma unroll
    for (int o = 16; o; o >>= 1) s += __shfl_xor_sync(0xffffffffu, s, o);
    if (lane == 0) out[row] = bias ? (s + bias[row]) : s;
}

// ---------------- softmax over L=4096 scores (single block, 1024 thr) ----------------
__global__ void softmax_kernel(float* __restrict__ a_out /* d_out + V + H (unaligned) */) {
    __shared__ float sh[32];
    __shared__ float bc;
    int t = threadIdx.x;

    float4 v = reinterpret_cast<const float4*>(g_e)[t];
    float m = fmaxf(fmaxf(v.x, v.y), fmaxf(v.z, v.w));
#pragma unroll
    for (int o = 16; o; o >>= 1) m = fmaxf(m, __shfl_xor_sync(0xffffffffu, m, o));
    if ((t & 31) == 0) sh[t >> 5] = m;
    __syncthreads();
    if (t < 32) {
        float x = sh[t];
#pragma unroll
        for (int o = 16; o; o >>= 1) x = fmaxf(x, __shfl_xor_sync(0xffffffffu, x, o));
        if (t == 0) bc = x;
    }
    __syncthreads();
    float M = bc;

    float4 ex;
    ex.x = expf(v.x - M); ex.y = expf(v.y - M);
    ex.z = expf(v.z - M); ex.w = expf(v.w - M);
    float s = ex.x + ex.y + ex.z + ex.w;
#pragma unroll
    for (int o = 16; o; o >>= 1) s += __shfl_xor_sync(0xffffffffu, s, o);
    __syncthreads();  // protect sh reuse
    if ((t & 31) == 0) sh[t >> 5] = s;
    __syncthreads();
    if (t < 32) {
        float x = sh[t];
#pragma unroll
        for (int o = 16; o; o >>= 1) x += __shfl_xor_sync(0xffffffffu, x, o);
        if (t == 0) bc = x;
    }
    __syncthreads();
    float inv = 1.0f / bc;
    ex.x *= inv; ex.y *= inv; ex.z *= inv; ex.w *= inv;

    reinterpret_cast<float4*>(g_a)[t] = ex;   // aligned copy for ctx kernel
    a_out[4 * t + 0] = ex.x;                  // output slot (unaligned base)
    a_out[4 * t + 1] = ex.y;
    a_out[4 * t + 2] = ex.z;
    a_out[4 * t + 3] = ex.w;
}

// ---------------- context: g_cat[H+j] += sum_l a[l] * h_all[l][j] ----------------
__global__ void ctx_kernel(const float* __restrict__ h_all) {
    int j = blockIdx.x * blockDim.x + threadIdx.x;  // 0..H-1 (grid.x = 4, 256 thr)
    const int CHUNK = LCTX / 32;                    // grid.y = 32
    int l0 = blockIdx.y * CHUNK;
    float s = 0.0f;
#pragma unroll 4
    for (int l = l0; l < l0 + CHUNK; ++l)
        s = fmaf(g_a[l], h_all[(size_t)l * H + j], s);
    atomicAdd(&g_cat[H + j], s);
}

// ---------------- GRU gates (single block, 1024 thr) ----------------
__global__ void gates_kernel(const float* __restrict__ s_prev,
                             float* __restrict__ h_out /* d_out + V */) {
    int i = threadIdx.x;
    float r = 1.0f / (1.0f + expf(-(g_gi[i] + g_gh[i])));
    float z = 1.0f / (1.0f + expf(-(g_gi[H + i] + g_gh[H + i])));
    float n = tanhf(g_gi[2 * H + i] + r * g_gh[2 * H + i]);
    float hv = (1.0f - z) * n + z * s_prev[i];
    g_h[i] = hv;      // aligned copy for logits GEMV
    h_out[i] = hv;    // output slot
}

// ---------------- in-place log-softmax over V logits (single block) ----------------
__global__ void logsoftmax_kernel(float* __restrict__ out) {
    __shared__ float sh[32];
    __shared__ float bc;
    int t = threadIdx.x;

    float m = -1e30f;
    for (int i = t; i < V; i += 1024) m = fmaxf(m, out[i]);
#pragma unroll
    for (int o = 16; o; o >>= 1) m = fmaxf(m, __shfl_xor_sync(0xffffffffu, m, o));
    if ((t & 31) == 0) sh[t >> 5] = m;
    __syncthreads();
    if (t < 32) {
        float x = sh[t];
#pragma unroll
        for (int o = 16; o; o >>= 1) x = fmaxf(x, __shfl_xor_sync(0xffffffffu, x, o));
        if (t == 0) bc = x;
    }
    __syncthreads();
    float M = bc;

    float s = 0.0f;
    for (int i = t; i < V; i += 1024) s += expf(out[i] - M);
#pragma unroll
    for (int o = 16; o; o >>= 1) s += __shfl_xor_sync(0xffffffffu, s, o);
    __syncthreads();
    if ((t & 31) == 0) sh[t >> 5] = s;
    __syncthreads();
    if (t < 32) {
        float x = sh[t];
#pragma unroll
        for (int o = 16; o; o >>= 1) x += __shfl_xor_sync(0xffffffffu, x, o);
        if (t == 0) bc = x;
    }
    __syncthreads();
    float ln = M + logf(bc);

    for (int i = t; i < V; i += 1024) out[i] -= ln;
}

// ---------------- launch ----------------
extern "C" void kernel_launch(void* const* d_in, const int* in_sizes, int n_in,
                              void* d_out, int out_size) {
    const int*   y      = (const int*)d_in[0];
    const float* s_bef  = (const float*)d_in[1];   // (1,1,H)
    const float* h_all  = (const float*)d_in[2];   // (L,H)
    const float* emb_W  = (const float*)d_in[3];   // (V,H)
    const float* alignW = (const float*)d_in[4];   // (1,2H) ; first H = Wh
    // d_in[5] align_b: scalar shift — softmax-invariant, unused
    const float* new_W  = (const float*)d_in[6];   // (H,2H)
    const float* new_b  = (const float*)d_in[7];
    const float* W_ih   = (const float*)d_in[8];   // (3H,H)
    const float* b_ih   = (const float*)d_in[9];
    const float* W_hh   = (const float*)d_in[10];  // (3H,H)
    const float* b_hh   = (const float*)d_in[11];
    const float* out_W  = (const float*)d_in[12];  // (V,H)
    const float* out_b  = (const float*)d_in[13];
    float* out = (float*)d_out;  // [logp(V) | h_new(H) | a(L)]

    float *p_e, *p_cat, *p_x, *p_gi, *p_gh, *p_h;
    cudaGetSymbolAddress((void**)&p_e,   g_e);
    cudaGetSymbolAddress((void**)&p_cat, g_cat);
    cudaGetSymbolAddress((void**)&p_x,   g_x);
    cudaGetSymbolAddress((void**)&p_gi,  g_gi);
    cudaGetSymbolAddress((void**)&p_gh,  g_gh);
    cudaGetSymbolAddress((void**)&p_h,   g_h);

    // independent of attention path: gh = W_hh @ s_prev + b_hh (issue early)
    gemv_kernel<H><<<(3 * H + 7) / 8, 256>>>(W_hh, s_bef, b_hh, p_gh, 3 * H);

    emb_kernel<<<2, 1024>>>(y, emb_W);

    // e[l] = h_all[l,:] . Wh      (scalar shift dropped: softmax-invariant)
    gemv_kernel<H><<<(LCTX + 7) / 8, 256>>>(h_all, alignW, nullptr, p_e, LCTX);

    softmax_kernel<<<1, 1024>>>(out + V + H);

    ctx_kernel<<<dim3(H / 256, 32), 256>>>(h_all);

    // x = new_W @ [emb; c] + new_b
    gemv_kernel<2 * H><<<(H + 7) / 8, 256>>>(new_W, p_cat, new_b, p_x, H);

    // gi = W_ih @ x + b_ih
    gemv_kernel<H><<<(3 * H + 7) / 8, 256>>>(W_ih, p_x, b_ih, p_gi, 3 * H);

    gates_kernel<<<1, 1024>>>(s_bef, out + V);

    // logits = out_W @ h_new + out_b   (the 206 MB streamer — the whole game)
    gemv_kernel<H><<<(V + 7) / 8, 256>>>(out_W, p_h, out_b, out, V);

    logsoftmax_kernel<<<1, 1024>>>(out);
}

// round 4
// speedup vs baseline: 1.2600x; 1.2600x over previous
#include <cuda_runtime.h>

#define H 1024
#define V 50257
#define LCTX 4096

#define NBLK 148          // <= SM count (GB300 has 152) -> all blocks co-resident
#define TPB  256
#define NW   (NBLK * 8)   // total warps in persistent kernel

// ---------------- device scratch (allocation-free, 16B aligned) ----------------
__device__ __align__(16) float g_e[LCTX];
__device__ __align__(16) float g_cat[2 * H];
__device__ __align__(16) float g_x[H];
__device__ __align__(16) float g_gh[3 * H];
__device__ __align__(16) float g_h[H];

__device__ unsigned g_bar_count = 0;
__device__ unsigned g_bar_gen   = 0;
__device__ unsigned g_maxkey    = 0;
__device__ float    g_sumexp    = 0.0f;

// order-preserving float->uint key
__device__ __forceinline__ unsigned flipf(float f) {
    unsigned u = __float_as_uint(f);
    return u ^ ((unsigned)((int)u >> 31) | 0x80000000u);
}
__device__ __forceinline__ float unflipf(unsigned k) {
    unsigned u = (k & 0x80000000u) ? (k ^ 0x80000000u) : ~k;
    return __uint_as_float(u);
}

__device__ __forceinline__ void grid_barrier() {
    __threadfence();
    __syncthreads();
    if (threadIdx.x == 0) {
        unsigned gen = *(volatile unsigned*)&g_bar_gen;
        if (atomicAdd(&g_bar_count, 1u) == NBLK - 1) {
            g_bar_count = 0;
            __threadfence();
            atomicExch(&g_bar_gen, gen + 1);
        } else {
            while (*(volatile unsigned*)&g_bar_gen == gen) {}
        }
        __threadfence();
    }
    __syncthreads();
}

__device__ __forceinline__ float warp_sum(float s) {
#pragma unroll
    for (int o = 16; o; o >>= 1) s += __shfl_xor_sync(0xffffffffu, s, o);
    return s;
}
__device__ __forceinline__ float warp_max(float s) {
#pragma unroll
    for (int o = 16; o; o >>= 1) s = fmaxf(s, __shfl_xor_sync(0xffffffffu, s, o));
    return s;
}

// ================= persistent fused chain =================
// phase1: e = h_all@Wh ; gh = W_hh@s_prev + b_hh ; emb gather ; zero ctx ; resets
// phase2: per-block softmax stats; ctx accumulation (atomics); write a to out
// phase3: x = new_W@[emb;c] + new_b
// phase4: gi = W_ih@x + b_ih fused with GRU gates -> h_new
__global__ void __launch_bounds__(TPB, 1)
chain_kernel(const int* __restrict__ y, const float* __restrict__ s_bef,
             const float* __restrict__ h_all, const float* __restrict__ emb_W,
             const float* __restrict__ alignW, const float* __restrict__ new_W,
             const float* __restrict__ new_b, const float* __restrict__ W_ih,
             const float* __restrict__ b_ih, const float* __restrict__ W_hh,
             const float* __restrict__ b_hh, float* __restrict__ out) {
    __shared__ float sbuf[2 * H];          // phase-dependent staging
    __shared__ float sred[33];

    const int t    = threadIdx.x;
    const int bid  = blockIdx.x;
    const int wid  = t >> 5;
    const int lane = t & 31;
    const int gw   = bid * 8 + wid;
    float4* sb4 = reinterpret_cast<float4*>(sbuf);

    // ---------- phase 1 ----------
    // stage Wh (first H of alignW) and s_prev in shared
    sb4[t]       = reinterpret_cast<const float4*>(alignW)[t];        // Wh
    sb4[256 + t] = reinterpret_cast<const float4*>(s_bef)[t];         // s_prev
    __syncthreads();

    if (bid == 0 && t == 0) { g_maxkey = 0u; g_sumexp = 0.0f; }
    if (bid == 1) {  // embedding gather -> g_cat[0..H)
        int yv = y[0];
        reinterpret_cast<float4*>(g_cat)[t] =
            reinterpret_cast<const float4*>(emb_W)[(size_t)yv * 256 + t];
    }
    if (bid == 2) {  // zero context accumulator
        reinterpret_cast<float4*>(g_cat)[256 + t] = make_float4(0.f, 0.f, 0.f, 0.f);
    }

    // rows 0..4095 -> e ; rows 4096..7167 -> gh
    for (int r = gw; r < LCTX + 3 * H; r += NW) {
        const float4* row;
        const float4* vec;
        if (r < LCTX) { row = reinterpret_cast<const float4*>(h_all) + (size_t)r * 256; vec = sb4; }
        else          { row = reinterpret_cast<const float4*>(W_hh) + (size_t)(r - LCTX) * 256; vec = sb4 + 256; }
        float s = 0.0f;
#pragma unroll
        for (int i = 0; i < 8; ++i) {
            float4 w = __ldg(&row[lane + i * 32]);
            float4 x = vec[lane + i * 32];
            s = fmaf(w.x, x.x, s); s = fmaf(w.y, x.y, s);
            s = fmaf(w.z, x.z, s); s = fmaf(w.w, x.w, s);
        }
        s = warp_sum(s);
        if (lane == 0) {
            if (r < LCTX) g_e[r] = s;
            else          g_gh[r - LCTX] = s + b_hh[r - LCTX];
        }
    }
    grid_barrier();

    // ---------- phase 2: softmax stats (redundant per block, L2-hot) ----------
    float m = -1e30f;
#pragma unroll
    for (int k = 0; k < 16; ++k) m = fmaxf(m, g_e[k * 256 + t]);
    m = warp_max(m);
    if (lane == 0) sred[wid] = m;
    __syncthreads();
    if (wid == 0) {
        float v = (lane < 8) ? sred[lane] : -1e30f;
        v = warp_max(v);
        if (lane == 0) sred[32] = v;
    }
    __syncthreads();
    const float M = sred[32];
    float s = 0.0f;
#pragma unroll
    for (int k = 0; k < 16; ++k) s += expf(g_e[k * 256 + t] - M);
    s = warp_sum(s);
    __syncthreads();
    if (lane == 0) sred[wid] = s;
    __syncthreads();
    if (wid == 0) {
        float v = (lane < 8) ? sred[lane] : 0.0f;
        v = warp_sum(v);
        if (lane == 0) sred[32] = v;
    }
    __syncthreads();
    const float invS = 1.0f / sred[32];
    __syncthreads();

    if (bid < 128) {
        // ctx: 32 l-chunks x 4 j-groups
        const int jg = bid & 3, l0 = (bid >> 2) * 128;
        if (t < 128) sbuf[t] = expf(g_e[l0 + t] - M) * invS;
        __syncthreads();
        const int j = jg * 256 + t;
        const float* hp = h_all + (size_t)l0 * H + j;
        float acc = 0.0f;
#pragma unroll 8
        for (int l = 0; l < 128; ++l) acc = fmaf(sbuf[l], hp[(size_t)l * H], acc);
        atomicAdd(&g_cat[H + j], acc);
    } else {
        // a -> output slot (unaligned base, scalar stores)
        float* a_out = out + V + H;
        int l = (bid - 128) * 205 + t;
        if (t < 205 && l < LCTX) a_out[l] = expf(g_e[l] - M) * invS;
    }
    grid_barrier();

    // ---------- phase 3: x = new_W @ cat + new_b ----------
    sb4[t]       = reinterpret_cast<const float4*>(g_cat)[t];
    sb4[256 + t] = reinterpret_cast<const float4*>(g_cat)[256 + t];
    __syncthreads();
    if (gw < H) {
        const float4* row = reinterpret_cast<const float4*>(new_W) + (size_t)gw * 512;
        float acc = 0.0f;
#pragma unroll
        for (int i = 0; i < 16; ++i) {
            float4 w = __ldg(&row[lane + i * 32]);
            float4 x = sb4[lane + i * 32];
            acc = fmaf(w.x, x.x, acc); acc = fmaf(w.y, x.y, acc);
            acc = fmaf(w.z, x.z, acc); acc = fmaf(w.w, x.w, acc);
        }
        acc = warp_sum(acc);
        if (lane == 0) g_x[gw] = acc + new_b[gw];
    }
    grid_barrier();

    // ---------- phase 4: gi = W_ih @ x + b_ih, fused GRU gates ----------
    sb4[t] = reinterpret_cast<const float4*>(g_x)[t];   // x (1024 floats)
    __syncthreads();
    if (gw < H) {
        float d[3];
#pragma unroll
        for (int g = 0; g < 3; ++g) {
            const float4* row = reinterpret_cast<const float4*>(W_ih) + (size_t)(gw + g * H) * 256;
            float acc = 0.0f;
#pragma unroll
            for (int i = 0; i < 8; ++i) {
                float4 w = __ldg(&row[lane + i * 32]);
                float4 x = sb4[lane + i * 32];
                acc = fmaf(w.x, x.x, acc); acc = fmaf(w.y, x.y, acc);
                acc = fmaf(w.z, x.z, acc); acc = fmaf(w.w, x.w, acc);
            }
            d[g] = warp_sum(acc);
        }
        if (lane == 0) {
            float gir = d[0] + b_ih[gw];
            float giz = d[1] + b_ih[gw + H];
            float gin = d[2] + b_ih[gw + 2 * H];
            float r = 1.0f / (1.0f + expf(-(gir + g_gh[gw])));
            float z = 1.0f / (1.0f + expf(-(giz + g_gh[gw + H])));
            float n = tanhf(gin + r * g_gh[gw + 2 * H]);
            float hv = (1.0f - z) * n + z * s_bef[gw];
            g_h[gw]  = hv;
            out[V + gw] = hv;
        }
    }
}

// ================= logits GEMV (the 206 MB streamer) + max epilogue =================
__global__ void logits_kernel(const float* __restrict__ W, const float* __restrict__ b,
                              float* __restrict__ out) {
    __shared__ float4 sh[256];
    __shared__ float smax[8];
    const int t = threadIdx.x, wid = t >> 5, lane = t & 31;
    sh[t] = reinterpret_cast<const float4*>(g_h)[t];
    __syncthreads();

    const int row = blockIdx.x * 8 + wid;
    float val = -1e30f;
    if (row < V) {
        const float4* Wr = reinterpret_cast<const float4*>(W) + (size_t)row * 256;
        float s = 0.0f;
#pragma unroll
        for (int i = 0; i < 8; ++i) {
            float4 w = __ldg(&Wr[lane + i * 32]);
            float4 x = sh[lane + i * 32];
            s = fmaf(w.x, x.x, s); s = fmaf(w.y, x.y, s);
            s = fmaf(w.z, x.z, s); s = fmaf(w.w, x.w, s);
        }
        s = warp_sum(s);
        if (lane == 0) { val = s + b[row]; out[row] = val; }
    }
    if (lane == 0) smax[wid] = val;
    __syncthreads();
    if (t == 0) {
        float m = smax[0];
#pragma unroll
        for (int i = 1; i < 8; ++i) m = fmaxf(m, smax[i]);
        atomicMax(&g_maxkey, flipf(m));
    }
}

// ================= parallel log-softmax: sum of exp, then subtract =================
__global__ void sumexp_kernel(const float* __restrict__ out) {
    __shared__ float sred[8];
    const int t = threadIdx.x, wid = t >> 5, lane = t & 31;
    const float M = unflipf(g_maxkey);
    float s = 0.0f;
    for (int i = blockIdx.x * TPB + t; i < V; i += gridDim.x * TPB)
        s += expf(out[i] - M);
    s = warp_sum(s);
    if (lane == 0) sred[wid] = s;
    __syncthreads();
    if (t == 0) {
        float v = sred[0];
#pragma unroll
        for (int i = 1; i < 8; ++i) v += sred[i];
        atomicAdd(&g_sumexp, v);
    }
}

__global__ void finalize_kernel(float* __restrict__ out) {
    const float ln = unflipf(g_maxkey) + logf(g_sumexp);
    for (int i = blockIdx.x * TPB + threadIdx.x; i < V; i += gridDim.x * TPB)
        out[i] -= ln;
}

// ================= launch =================
extern "C" void kernel_launch(void* const* d_in, const int* in_sizes, int n_in,
                              void* d_out, int out_size) {
    const int*   y      = (const int*)d_in[0];
    const float* s_bef  = (const float*)d_in[1];
    const float* h_all  = (const float*)d_in[2];
    const float* emb_W  = (const float*)d_in[3];
    const float* alignW = (const float*)d_in[4];
    // d_in[5] align_b: uniform shift, softmax-invariant -> dropped
    const float* new_W  = (const float*)d_in[6];
    const float* new_b  = (const float*)d_in[7];
    const float* W_ih   = (const float*)d_in[8];
    const float* b_ih   = (const float*)d_in[9];
    const float* W_hh   = (const float*)d_in[10];
    const float* b_hh   = (const float*)d_in[11];
    const float* out_W  = (const float*)d_in[12];
    const float* out_b  = (const float*)d_in[13];
    float* out = (float*)d_out;  // [logp(V) | h_new(H) | a(L)]

    chain_kernel<<<NBLK, TPB>>>(y, s_bef, h_all, emb_W, alignW, new_W, new_b,
                                W_ih, b_ih, W_hh, b_hh, out);
    logits_kernel<<<(V + 7) / 8, TPB>>>(out_W, out_b, out);
    sumexp_kernel<<<112, TPB>>>(out);
    finalize_kernel<<<112, TPB>>>(out);
}